// round 13
// baseline (speedup 1.0000x reference)
#include <cuda_runtime.h>
#include <cuda_fp16.h>
#include <stdint.h>
#include <math.h>

// ---------------- problem constants ----------------------------------------
#define BB   8
#define CC   512
#define SS   256
#define TT   8192
#define DIL  4
#define NTOT (BB*TT)       // 65536
#define K1   (2*CC)        // 1024 reduction dim GEMM1
#define M1   (2*CC)        // 1024 rows of W1 (F/G interleaved)
#define M2   (CC+SS)       // 768 rows GEMM2
#define KC   64            // k halfs per smem stage (4 mma k-steps of 16)
#define HST  72            // smem row stride in halfs (144B): conflict-free
#define NST  3             // pipeline stages
#define SZT  72            // gemm1 z-staging stride (halfs)
#define SFT  132           // gemm2 out-staging stride (floats)
#define SQRT_HALF 0.70710678118654752440f

// ---------------- device scratch --------------------------------------------
__device__ __align__(16) __half g_xT[(size_t)NTOT*CC];  // [b][t][c]
__device__ __align__(16) __half g_zT[(size_t)NTOT*CC];  // [b][t][c]
__device__ __align__(16) __half g_W1[M1*K1];            // [o=2c+g][k]
__device__ __align__(16) __half g_W2[M2*CC];            // [m][k]
__device__ __align__(16) __half g_zero[16];             // zero-init (causal pad)

// ---------------- helpers ----------------------------------------------------
__device__ __forceinline__ void mma16(float* c, const uint32_t* a, const uint32_t* b) {
    asm volatile(
        "mma.sync.aligned.m16n8k16.row.col.f32.f16.f16.f32 "
        "{%0,%1,%2,%3}, {%4,%5,%6,%7}, {%8,%9}, {%0,%1,%2,%3};"
        : "+f"(c[0]), "+f"(c[1]), "+f"(c[2]), "+f"(c[3])
        : "r"(a[0]), "r"(a[1]), "r"(a[2]), "r"(a[3]), "r"(b[0]), "r"(b[1]));
}
__device__ __forceinline__ void cpa16(uint32_t dst, const void* src) {
    asm volatile("cp.async.cg.shared.global [%0], [%1], 16;" :: "r"(dst), "l"(src));
}
#define CP_COMMIT() asm volatile("cp.async.commit_group;" ::: "memory")
#define CP_WAIT1()  asm volatile("cp.async.wait_group 1;" ::: "memory")

#define STAGE (128*HST)                     // halfs per operand stage
#define SMEM_DYN (2*NST*STAGE*2)            // bytes: A[NST] + B[NST] (110592)

// ---------------- transpose: x[b][c][t] fp32 -> xT[b][t][c] fp16 -------------
__global__ void __launch_bounds__(256)
transpose_x(const float* __restrict__ x) {
    __shared__ float tile[64][65];
    const int b = blockIdx.z, c0 = blockIdx.y * 64, t0 = blockIdx.x * 64;
    const int tid = threadIdx.x;
    {
        const int row = tid >> 2, seg = (tid & 3) * 16;
        const float* src = x + ((size_t)b * CC + c0 + row) * TT + t0 + seg;
        #pragma unroll
        for (int i = 0; i < 4; i++) {
            float4 v = *(const float4*)(src + i * 4);
            tile[row][seg + i * 4 + 0] = v.x;
            tile[row][seg + i * 4 + 1] = v.y;
            tile[row][seg + i * 4 + 2] = v.z;
            tile[row][seg + i * 4 + 3] = v.w;
        }
    }
    __syncthreads();
    {
        const int trow = tid >> 2, seg = (tid & 3) * 16;
        __half* dst = g_xT + ((size_t)b * TT + t0 + trow) * CC + c0 + seg;
        #pragma unroll
        for (int i = 0; i < 2; i++) {
            __half h[8];
            #pragma unroll
            for (int j = 0; j < 8; j++)
                h[j] = __float2half_rn(tile[seg + i * 8 + j][trow]);
            *(uint4*)(dst + i * 8) = *(const uint4*)h;
        }
    }
}

// ---------------- merged weight pack -----------------------------------------
__global__ void pack_w(const float* __restrict__ fw, const float* __restrict__ gw,
                       const float* __restrict__ rw, const float* __restrict__ sw) {
    int idx = blockIdx.x * blockDim.x + threadIdx.x;
    if (idx < M1 * K1) {
        int o = idx / K1, k = idx % K1;
        int co = o >> 1, ci = k & (CC - 1);
        int tap = (k < CC) ? 1 : 0;
        const float* w = (o & 1) ? gw : fw;
        g_W1[idx] = __float2half_rn(w[(co * CC + ci) * 2 + tap]);
    }
    if (idx < M2 * CC) {
        int m = idx / CC, k = idx % CC;
        g_W2[idx] = __float2half_rn((m < CC) ? rw[m * CC + k] : sw[(m - CC) * CC + k]);
    }
}

// ---------------- GEMM1: D[t][2c+g] = xT2 @ W1^T, fused gating --------------
__global__ void __launch_bounds__(256, 2)
gemm1(const float* __restrict__ fbias, const float* __restrict__ gbias)
{
    extern __shared__ __half hsm[];
    __half* sA = hsm;                  // [NST][128*HST]
    __half* sB = hsm + NST * STAGE;

    const int tid = threadIdx.x, lane = tid & 31, wid = tid >> 5;
    const int wm = wid >> 2, wn = wid & 3;
    const int nb = blockIdx.x;                    // 8 outch-tiles
    const int tb = blockIdx.y;                    // 512 t-tiles
    const int base = tb * 128;
    const int b = base / TT;
    const int t0 = base % TT;
    const int n0 = nb * 128;
    const __half* __restrict__ xTb = g_xT + (size_t)b * TT * CC;

    const uint32_t sA_u = (uint32_t)__cvta_generic_to_shared(sA);
    const uint32_t sB_u = (uint32_t)__cvta_generic_to_shared(sB);

    float acc[4][4][4];
    #pragma unroll
    for (int i = 0; i < 4; i++)
        #pragma unroll
        for (int j = 0; j < 4; j++)
            #pragma unroll
            for (int q = 0; q < 4; q++) acc[i][j][q] = 0.f;

    const int arow = tid >> 3, ac8 = (tid & 7) * 8;
    auto issue = [&](int st, int k0) {
        const int sh = (k0 >= CC) ? DIL : 0;
        const int kk = k0 & (CC - 1);
        #pragma unroll
        for (int i = 0; i < 4; i++) {
            int row = arow + i * 32;
            int t = t0 + row - sh;
            const __half* srcA = (t >= 0) ? &xTb[(size_t)t * CC + kk + ac8]
                                          : &g_zero[0];
            cpa16(sA_u + (st * STAGE + row * HST + ac8) * 2, srcA);
            cpa16(sB_u + (st * STAGE + row * HST + ac8) * 2,
                  &g_W1[(size_t)(n0 + row) * K1 + k0 + ac8]);
        }
    };

    issue(0, 0);  CP_COMMIT();
    issue(1, KC); CP_COMMIT();

    const int aoff = (wm * 64 + (lane >> 2)) * HST + (lane & 3) * 2;
    const int boff = (wn * 32 + (lane >> 2)) * HST + (lane & 3) * 2;

    const int NC = K1 / KC;   // 16
    int st = 0;
    for (int c = 0; c < NC; c++) {
        CP_WAIT1();
        __syncthreads();
        const __half* a  = sA + st * STAGE + aoff;
        const __half* bs = sB + st * STAGE + boff;
        #pragma unroll
        for (int ks = 0; ks < 4; ks++) {
            const int kc = ks * 16;
            uint32_t af[4][4], bf[4][2];
            #pragma unroll
            for (int mi = 0; mi < 4; mi++) {
                const __half* p = a + mi * 16 * HST + kc;
                af[mi][0] = *(const uint32_t*)(p);
                af[mi][1] = *(const uint32_t*)(p + 8 * HST);
                af[mi][2] = *(const uint32_t*)(p + 8);
                af[mi][3] = *(const uint32_t*)(p + 8 * HST + 8);
            }
            #pragma unroll
            for (int ni = 0; ni < 4; ni++) {
                const __half* p = bs + ni * 8 * HST + kc;
                bf[ni][0] = *(const uint32_t*)(p);
                bf[ni][1] = *(const uint32_t*)(p + 8);
            }
            #pragma unroll
            for (int mi = 0; mi < 4; mi++)
                #pragma unroll
                for (int ni = 0; ni < 4; ni++)
                    mma16(acc[mi][ni], af[mi], bf[ni]);
        }
        __syncthreads();
        if (c + 2 < NC) issue((c + 2) % NST, (c + 2) * KC);
        CP_COMMIT();
        st = (st + 1) % NST;
    }
    // last iteration ended with a __syncthreads after all fragment reads:
    // pipeline smem is safe to reuse for staging.

    // ---- epilogue: gate -> smem stage -> coalesced 16B row writes -----------
    __half* sz = hsm;                             // [128][SZT]
    #pragma unroll
    for (int mi = 0; mi < 4; mi++) {
        const int tl = wm * 64 + mi * 16 + (lane >> 2);
        #pragma unroll
        for (int ni = 0; ni < 4; ni++) {
            const int chl = wn * 16 + ni * 4 + (lane & 3);
            const int ch = nb * 64 + chl;
            const float fb = fbias[ch], gb = gbias[ch];
            float F0 = acc[mi][ni][0] + fb;
            float G0 = acc[mi][ni][1] + gb;
            float F1 = acc[mi][ni][2] + fb;
            float G1 = acc[mi][ni][3] + gb;
            sz[tl * SZT + chl] =
                __float2half_rn(tanhf(F0) * (1.f / (1.f + __expf(-G0))));
            sz[(tl + 8) * SZT + chl] =
                __float2half_rn(tanhf(F1) * (1.f / (1.f + __expf(-G1))));
        }
    }
    __syncthreads();
    __half* __restrict__ zb = g_zT + (size_t)b * TT * CC;
    #pragma unroll
    for (int i = 0; i < 4; i++) {
        int f4 = tid + i * 256;
        int trow = f4 >> 3, c8 = f4 & 7;          // 8 uint4 per 64-half row
        *(uint4*)&zb[(size_t)(t0 + trow) * CC + nb * 64 + c8 * 8] =
            *(const uint4*)&sz[trow * SZT + c8 * 8];
    }
}

// ---------------- GEMM2: D[m][t] = W2 @ zT^T, fused residual/skip -----------
__global__ void __launch_bounds__(256, 2)
gemm2(const float* __restrict__ x,
      const float* __restrict__ rbias, const float* __restrict__ sbias,
      float* __restrict__ out)
{
    extern __shared__ __half hsm[];
    __half* sA = hsm;
    __half* sB = hsm + NST * STAGE;

    const int tid = threadIdx.x, lane = tid & 31, wid = tid >> 5;
    const int wm = wid >> 2, wn = wid & 3;
    const int mb = blockIdx.x;                    // 6 m-tiles
    const int tb = blockIdx.y;                    // 512 t-tiles
    const int base = tb * 128;
    const int b = base / TT;
    const int t0 = base % TT;
    const int m0 = mb * 128;
    const __half* __restrict__ zTb = g_zT + (size_t)b * TT * CC;

    const uint32_t sA_u = (uint32_t)__cvta_generic_to_shared(sA);
    const uint32_t sB_u = (uint32_t)__cvta_generic_to_shared(sB);

    float acc[4][4][4];
    #pragma unroll
    for (int i = 0; i < 4; i++)
        #pragma unroll
        for (int j = 0; j < 4; j++)
            #pragma unroll
            for (int q = 0; q < 4; q++) acc[i][j][q] = 0.f;

    const int arow = tid >> 3, ac8 = (tid & 7) * 8;
    auto issue = [&](int st, int k0) {
        #pragma unroll
        for (int i = 0; i < 4; i++) {
            int row = arow + i * 32;
            cpa16(sA_u + (st * STAGE + row * HST + ac8) * 2,
                  &g_W2[(size_t)(m0 + row) * CC + k0 + ac8]);
            cpa16(sB_u + (st * STAGE + row * HST + ac8) * 2,
                  &zTb[(size_t)(t0 + row) * CC + k0 + ac8]);
        }
    };

    issue(0, 0);  CP_COMMIT();
    issue(1, KC); CP_COMMIT();

    const int aoff = (wm * 64 + (lane >> 2)) * HST + (lane & 3) * 2;
    const int boff = (wn * 32 + (lane >> 2)) * HST + (lane & 3) * 2;

    const int NC = CC / KC;   // 8
    int st = 0;
    for (int c = 0; c < NC; c++) {
        CP_WAIT1();
        __syncthreads();
        const __half* a  = sA + st * STAGE + aoff;
        const __half* bs = sB + st * STAGE + boff;
        #pragma unroll
        for (int ks = 0; ks < 4; ks++) {
            const int kc = ks * 16;
            uint32_t af[4][4], bf[4][2];
            #pragma unroll
            for (int mi = 0; mi < 4; mi++) {
                const __half* p = a + mi * 16 * HST + kc;
                af[mi][0] = *(const uint32_t*)(p);
                af[mi][1] = *(const uint32_t*)(p + 8 * HST);
                af[mi][2] = *(const uint32_t*)(p + 8);
                af[mi][3] = *(const uint32_t*)(p + 8 * HST + 8);
            }
            #pragma unroll
            for (int ni = 0; ni < 4; ni++) {
                const __half* p = bs + ni * 8 * HST + kc;
                bf[ni][0] = *(const uint32_t*)(p);
                bf[ni][1] = *(const uint32_t*)(p + 8);
            }
            #pragma unroll
            for (int mi = 0; mi < 4; mi++)
                #pragma unroll
                for (int ni = 0; ni < 4; ni++)
                    mma16(acc[mi][ni], af[mi], bf[ni]);
        }
        __syncthreads();
        if (c + 2 < NC) issue((c + 2) % NST, (c + 2) * KC);
        CP_COMMIT();
        st = (st + 1) % NST;
    }
    // pipeline smem safe to reuse (sync after last fragment reads).

    // ---- epilogue: stage fp32 tile in smem, warp-per-row coalesced writeback
    float* sf = (float*)hsm;                      // [128][SFT] = 67.6 KB
    #pragma unroll
    for (int mi = 0; mi < 4; mi++) {
        #pragma unroll
        for (int half = 0; half < 2; half++) {
            const int r = wm * 64 + mi * 16 + (lane >> 2) + half * 8;
            #pragma unroll
            for (int ni = 0; ni < 4; ni++) {
                const int cc = wn * 32 + ni * 8 + (lane & 3) * 2;
                float2 v;
                v.x = acc[mi][ni][half * 2];
                v.y = acc[mi][ni][half * 2 + 1];
                *(float2*)&sf[r * SFT + cc] = v;
            }
        }
    }
    __syncthreads();
    // 128 rows x 32 float4; one warp covers exactly one row per iteration.
    #pragma unroll
    for (int i = 0; i < 16; i++) {
        int f4 = tid + i * 256;
        int r = f4 >> 5, c4 = f4 & 31;
        int m = m0 + r;
        float4 v = *(const float4*)&sf[r * SFT + c4 * 4];
        if (m < CC) {
            const float rbv = rbias[m];
            size_t goff = ((size_t)b * CC + m) * TT + t0 + c4 * 4;
            float4 xv = *(const float4*)&x[goff];
            float4 o;
            o.x = (xv.x + v.x + rbv) * SQRT_HALF;
            o.y = (xv.y + v.y + rbv) * SQRT_HALF;
            o.z = (xv.z + v.z + rbv) * SQRT_HALF;
            o.w = (xv.w + v.w + rbv) * SQRT_HALF;
            *(float4*)&out[goff] = o;
        } else {
            const int s = m - CC;
            const float sbv = sbias[s];
            size_t goff = (size_t)BB * CC * TT + ((size_t)b * SS + s) * TT + t0 + c4 * 4;
            float4 o = make_float4(v.x + sbv, v.y + sbv, v.z + sbv, v.w + sbv);
            *(float4*)&out[goff] = o;
        }
    }
}

// ---------------- launch -----------------------------------------------------
extern "C" void kernel_launch(void* const* d_in, const int* in_sizes, int n_in,
                              void* d_out, int out_size)
{
    const float* x  = (const float*)d_in[0];
    const float* fw = (const float*)d_in[1];
    const float* fb = (const float*)d_in[2];
    const float* gw = (const float*)d_in[3];
    const float* gb = (const float*)d_in[4];
    const float* rw = (const float*)d_in[5];
    const float* rb = (const float*)d_in[6];
    const float* sw = (const float*)d_in[7];
    const float* sb = (const float*)d_in[8];
    float* out = (float*)d_out;

    cudaFuncSetAttribute(gemm1, cudaFuncAttributeMaxDynamicSharedMemorySize, SMEM_DYN);
    cudaFuncSetAttribute(gemm2, cudaFuncAttributeMaxDynamicSharedMemorySize, SMEM_DYN);

    transpose_x<<<dim3(TT / 64, CC / 64, BB), 256>>>(x);
    pack_w<<<(M1 * K1 + 255) / 256, 256>>>(fw, gw, rw, sw);
    gemm1<<<dim3(M1 / 128, NTOT / 128), 256, SMEM_DYN>>>(fb, gb);
    gemm2<<<dim3(M2 / 128, NTOT / 128), 256, SMEM_DYN>>>(x, rb, sb, out);
}

// round 14
// speedup vs baseline: 1.0200x; 1.0200x over previous
#include <cuda_runtime.h>
#include <cuda_fp16.h>
#include <stdint.h>
#include <math.h>

// ---------------- problem constants ----------------------------------------
#define BB   8
#define CC   512
#define SS   256
#define TT   8192
#define DIL  4
#define NTOT (BB*TT)       // 65536
#define K1   (2*CC)        // 1024 reduction dim GEMM1
#define M1   (2*CC)        // 1024 rows of W1 (F/G interleaved)
#define M2   (CC+SS)       // 768 rows GEMM2
#define KC   64            // k halfs per smem stage (4 mma k-steps of 16)
#define HST  72            // smem row stride in halfs (144B): conflict-free
#define NST  3             // pipeline stages
#define SQRT_HALF 0.70710678118654752440f

// ---------------- device scratch --------------------------------------------
__device__ __align__(16) __half g_xT[(size_t)NTOT*CC];  // [b][t][c]
__device__ __align__(16) __half g_zT[(size_t)NTOT*CC];  // [b][t][c]
__device__ __align__(16) __half g_W1[M1*K1];            // [o=2c+g][k]
__device__ __align__(16) __half g_W2[M2*CC];            // [m][k]
__device__ __align__(16) __half g_zero[16];             // zero-init (causal pad)

// ---------------- helpers ----------------------------------------------------
__device__ __forceinline__ void mma16(float* c, const uint32_t* a, const uint32_t* b) {
    asm volatile(
        "mma.sync.aligned.m16n8k16.row.col.f32.f16.f16.f32 "
        "{%0,%1,%2,%3}, {%4,%5,%6,%7}, {%8,%9}, {%0,%1,%2,%3};"
        : "+f"(c[0]), "+f"(c[1]), "+f"(c[2]), "+f"(c[3])
        : "r"(a[0]), "r"(a[1]), "r"(a[2]), "r"(a[3]), "r"(b[0]), "r"(b[1]));
}
__device__ __forceinline__ void cpa16(uint32_t dst, const void* src) {
    asm volatile("cp.async.cg.shared.global [%0], [%1], 16;" :: "r"(dst), "l"(src));
}
#define CP_COMMIT() asm volatile("cp.async.commit_group;" ::: "memory")
#define CP_WAIT1()  asm volatile("cp.async.wait_group 1;" ::: "memory")
#define CP_WAIT0()  asm volatile("cp.async.wait_group 0;" ::: "memory")

#define STAGE (128*HST)                     // halfs per operand stage (9216)
#define STAGE_B 18432                       // bytes per operand stage
#define SMEM_DYN (2*NST*STAGE*2)            // bytes: A[NST] + B[NST] (110592)

// ---------------- transpose: x[b][c][t] fp32 -> xT[b][t][c] fp16 -------------
__global__ void __launch_bounds__(256)
transpose_x(const float* __restrict__ x) {
    __shared__ float tile[64][65];
    const int b = blockIdx.z, c0 = blockIdx.y * 64, t0 = blockIdx.x * 64;
    const int tid = threadIdx.x;
    {
        const int row = tid >> 2, seg = (tid & 3) * 16;
        const float* src = x + ((size_t)b * CC + c0 + row) * TT + t0 + seg;
        #pragma unroll
        for (int i = 0; i < 4; i++) {
            float4 v = *(const float4*)(src + i * 4);
            tile[row][seg + i * 4 + 0] = v.x;
            tile[row][seg + i * 4 + 1] = v.y;
            tile[row][seg + i * 4 + 2] = v.z;
            tile[row][seg + i * 4 + 3] = v.w;
        }
    }
    __syncthreads();
    {
        const int trow = tid >> 2, seg = (tid & 3) * 16;
        __half* dst = g_xT + ((size_t)b * TT + t0 + trow) * CC + c0 + seg;
        #pragma unroll
        for (int i = 0; i < 2; i++) {
            __half h[8];
            #pragma unroll
            for (int j = 0; j < 8; j++)
                h[j] = __float2half_rn(tile[seg + i * 8 + j][trow]);
            *(uint4*)(dst + i * 8) = *(const uint4*)h;
        }
    }
}

// ---------------- merged weight pack -----------------------------------------
__global__ void pack_w(const float* __restrict__ fw, const float* __restrict__ gw,
                       const float* __restrict__ rw, const float* __restrict__ sw) {
    int idx = blockIdx.x * blockDim.x + threadIdx.x;
    if (idx < M1 * K1) {
        int o = idx / K1, k = idx % K1;
        int co = o >> 1, ci = k & (CC - 1);
        int tap = (k < CC) ? 1 : 0;
        const float* w = (o & 1) ? gw : fw;
        g_W1[idx] = __float2half_rn(w[(co * CC + ci) * 2 + tap]);
    }
    if (idx < M2 * CC) {
        int m = idx / CC, k = idx % CC;
        g_W2[idx] = __float2half_rn((m < CC) ? rw[m * CC + k] : sw[(m - CC) * CC + k]);
    }
}

// ---------------- GEMM1: D[t][2c+g] = xT2 @ W1^T, fused gating --------------
// CTA 128(t) x 128(interleaved outch); 8 warps 2x4; warp tile 64x32. fp16 MMA.
__global__ void __launch_bounds__(256, 2)
gemm1(const float* __restrict__ fbias, const float* __restrict__ gbias)
{
    extern __shared__ __half hsm[];
    __half* sA = hsm;                  // [NST][128*HST]
    __half* sB = hsm + NST * STAGE;

    const int tid = threadIdx.x, lane = tid & 31, wid = tid >> 5;
    const int wm = wid >> 2, wn = wid & 3;
    const int nb = blockIdx.x;
    const int tb = blockIdx.y;
    const int base = tb * 128;
    const int b = base / TT;
    const int t0 = base % TT;
    const int n0 = nb * 128;
    const __half* __restrict__ xTb = g_xT + (size_t)b * TT * CC;

    const uint32_t sA_u = (uint32_t)__cvta_generic_to_shared(sA);
    const uint32_t sB_u = (uint32_t)__cvta_generic_to_shared(sB);

    float acc[4][4][4];
    #pragma unroll
    for (int i = 0; i < 4; i++)
        #pragma unroll
        for (int j = 0; j < 4; j++)
            #pragma unroll
            for (int q = 0; q < 4; q++) acc[i][j][q] = 0.f;

    const int arow = tid >> 3, ac8 = (tid & 7) * 8;
    auto issue = [&](int st, int k0) {
        const int sh = (k0 >= CC) ? DIL : 0;
        const int kk = k0 & (CC - 1);
        #pragma unroll
        for (int i = 0; i < 4; i++) {
            int row = arow + i * 32;
            int t = t0 + row - sh;
            const __half* srcA = (t >= 0) ? &xTb[(size_t)t * CC + kk + ac8]
                                          : &g_zero[0];
            cpa16(sA_u + (st * STAGE + row * HST + ac8) * 2, srcA);
            cpa16(sB_u + (st * STAGE + row * HST + ac8) * 2,
                  &g_W1[(size_t)(n0 + row) * K1 + k0 + ac8]);
        }
    };

    issue(0, 0);  CP_COMMIT();
    issue(1, KC); CP_COMMIT();

    const int aoff = (wm * 64 + (lane >> 2)) * HST + (lane & 3) * 2;
    const int boff = (wn * 32 + (lane >> 2)) * HST + (lane & 3) * 2;

    const int NC = K1 / KC;   // 16
    int st = 0;
    for (int c = 0; c < NC; c++) {
        CP_WAIT1();
        __syncthreads();
        const __half* a  = sA + st * STAGE + aoff;
        const __half* bs = sB + st * STAGE + boff;
        #pragma unroll
        for (int ks = 0; ks < 4; ks++) {
            const int kc = ks * 16;
            uint32_t af[4][4], bf[4][2];
            #pragma unroll
            for (int mi = 0; mi < 4; mi++) {
                const __half* p = a + mi * 16 * HST + kc;
                af[mi][0] = *(const uint32_t*)(p);
                af[mi][1] = *(const uint32_t*)(p + 8 * HST);
                af[mi][2] = *(const uint32_t*)(p + 8);
                af[mi][3] = *(const uint32_t*)(p + 8 * HST + 8);
            }
            #pragma unroll
            for (int ni = 0; ni < 4; ni++) {
                const __half* p = bs + ni * 8 * HST + kc;
                bf[ni][0] = *(const uint32_t*)(p);
                bf[ni][1] = *(const uint32_t*)(p + 8);
            }
            #pragma unroll
            for (int mi = 0; mi < 4; mi++)
                #pragma unroll
                for (int ni = 0; ni < 4; ni++)
                    mma16(acc[mi][ni], af[mi], bf[ni]);
        }
        __syncthreads();
        if (c + 2 < NC) issue((c + 2) % NST, (c + 2) * KC);
        CP_COMMIT();
        st = (st + 1) % NST;
    }

    // ---- epilogue: (c0,c1)=(F,G) at row t; (c2,c3) at t+8 -------------------
    __half* __restrict__ zb = g_zT + (size_t)b * TT * CC;
    #pragma unroll
    for (int mi = 0; mi < 4; mi++) {
        const int t_lo = t0 + wm * 64 + mi * 16 + (lane >> 2);
        #pragma unroll
        for (int ni = 0; ni < 4; ni++) {
            const int ch = (n0 >> 1) + wn * 16 + ni * 4 + (lane & 3);
            const float fb = fbias[ch], gb = gbias[ch];
            float F0 = acc[mi][ni][0] + fb;
            float G0 = acc[mi][ni][1] + gb;
            float F1 = acc[mi][ni][2] + fb;
            float G1 = acc[mi][ni][3] + gb;
            zb[(size_t)t_lo * CC + ch] =
                __float2half_rn(tanhf(F0) * (1.f / (1.f + __expf(-G0))));
            zb[(size_t)(t_lo + 8) * CC + ch] =
                __float2half_rn(tanhf(F1) * (1.f / (1.f + __expf(-G1))));
        }
    }
}

// ---------------- GEMM2: D[m][t] = W2 @ zT^T, fused residual/skip -----------
// CTA 128(m) x 128(t); 8 warps 2x4; warp tile 64x32. fp16 MMA.
// Residual x tile prefetched into freed pipeline stages during final 2 chunks.
__global__ void __launch_bounds__(256, 2)
gemm2(const float* __restrict__ x,
      const float* __restrict__ rbias, const float* __restrict__ sbias,
      float* __restrict__ out)
{
    extern __shared__ __half hsm[];
    __half* sA = hsm;
    __half* sB = hsm + NST * STAGE;

    const int tid = threadIdx.x, lane = tid & 31, wid = tid >> 5;
    const int wm = wid >> 2, wn = wid & 3;
    const int mb = blockIdx.x;                    // 6 m-tiles
    const int tb = blockIdx.y;                    // 512 t-tiles
    const int base = tb * 128;
    const int b = base / TT;
    const int t0 = base % TT;
    const int m0 = mb * 128;
    const bool isRes = (m0 < CC);                 // whole tile residual or skip
    const __half* __restrict__ zTb = g_zT + (size_t)b * TT * CC;

    const uint32_t sA_u = (uint32_t)__cvta_generic_to_shared(sA);
    const uint32_t sB_u = (uint32_t)__cvta_generic_to_shared(sB);

    // x staging byte offset for row r (512B rows packed into freed stages:
    // rows 0-35 -> A stage2, 36-71 -> B stage2, 72-107 -> A stage0, 108-127 -> B stage0)
    auto xoff = [](int r) -> uint32_t {
        if (r < 36)  return 2u * STAGE_B + (uint32_t)r * 512u;
        if (r < 72)  return 3u * STAGE_B + 2u * STAGE_B + (uint32_t)(r - 36) * 512u;
        if (r < 108) return (uint32_t)(r - 72) * 512u;
        return 3u * STAGE_B + (uint32_t)(r - 108) * 512u;
    };

    float acc[4][4][4];
    #pragma unroll
    for (int i = 0; i < 4; i++)
        #pragma unroll
        for (int j = 0; j < 4; j++)
            #pragma unroll
            for (int q = 0; q < 4; q++) acc[i][j][q] = 0.f;

    const int arow = tid >> 3, ac8 = (tid & 7) * 8;
    auto issue = [&](int st, int k0) {
        #pragma unroll
        for (int i = 0; i < 4; i++) {
            int row = arow + i * 32;
            cpa16(sA_u + (st * STAGE + row * HST + ac8) * 2,
                  &g_W2[(size_t)(m0 + row) * CC + k0 + ac8]);
            cpa16(sB_u + (st * STAGE + row * HST + ac8) * 2,
                  &zTb[(size_t)(t0 + row) * CC + k0 + ac8]);
        }
    };

    issue(0, 0);  CP_COMMIT();
    issue(1, KC); CP_COMMIT();

    const int aoff = (wm * 64 + (lane >> 2)) * HST + (lane & 3) * 2;
    const int boff = (wn * 32 + (lane >> 2)) * HST + (lane & 3) * 2;

    const int NC = CC / KC;   // 8
    int st = 0;
    for (int c = 0; c < NC; c++) {
        CP_WAIT1();
        __syncthreads();
        const __half* a  = sA + st * STAGE + aoff;
        const __half* bs = sB + st * STAGE + boff;
        #pragma unroll
        for (int ks = 0; ks < 4; ks++) {
            const int kc = ks * 16;
            uint32_t af[4][4], bf[4][2];
            #pragma unroll
            for (int mi = 0; mi < 4; mi++) {
                const __half* p = a + mi * 16 * HST + kc;
                af[mi][0] = *(const uint32_t*)(p);
                af[mi][1] = *(const uint32_t*)(p + 8 * HST);
                af[mi][2] = *(const uint32_t*)(p + 8);
                af[mi][3] = *(const uint32_t*)(p + 8 * HST + 8);
            }
            #pragma unroll
            for (int ni = 0; ni < 4; ni++) {
                const __half* p = bs + ni * 8 * HST + kc;
                bf[ni][0] = *(const uint32_t*)(p);
                bf[ni][1] = *(const uint32_t*)(p + 8);
            }
            #pragma unroll
            for (int mi = 0; mi < 4; mi++)
                #pragma unroll
                for (int ni = 0; ni < 4; ni++)
                    mma16(acc[mi][ni], af[mi], bf[ni]);
        }
        __syncthreads();
        if (c + 2 < NC) {
            issue((c + 2) % NST, (c + 2) * KC);
        } else if (isRes) {
            // prefetch x rows into freed stages: part1 at c=NC-2, part2 at c=NC-1
            const int r0 = (c == NC - 2) ? 0 : 72;
            const int nops = ((c == NC - 2) ? 72 : 56) * 32;  // 32 cpa16 per row
            for (int i = tid; i < nops; i += 256) {
                const int r = r0 + (i >> 5);
                const int l16 = i & 31;
                cpa16(sA_u + xoff(r) + l16 * 16,
                      &x[((size_t)b * CC + m0 + r) * TT + t0 + l16 * 4]);
            }
        }
        CP_COMMIT();
        st = (st + 1) % NST;
    }

    // ---- epilogue: rows m (channels), cols t ---------------------------------
    if (isRes) {
        CP_WAIT0();
        __syncthreads();                           // x staging visible to all
        const char* sxb = (const char*)hsm;
        #pragma unroll
        for (int mi = 0; mi < 4; mi++) {
            #pragma unroll
            for (int half = 0; half < 2; half++) {
                const int r = wm * 64 + mi * 16 + (lane >> 2) + half * 8;
                const int m = m0 + r;
                const float rbv = rbias[m];
                float* __restrict__ orow = out + ((size_t)b * CC + m) * TT;
                const uint32_t xo = xoff(r);
                #pragma unroll
                for (int ni = 0; ni < 4; ni++) {
                    const int tcol = wn * 32 + ni * 8 + (lane & 3) * 2;
                    float2 xv = *(const float2*)(sxb + xo + tcol * 4);
                    float2 o;
                    o.x = (xv.x + acc[mi][ni][half * 2]     + rbv) * SQRT_HALF;
                    o.y = (xv.y + acc[mi][ni][half * 2 + 1] + rbv) * SQRT_HALF;
                    *(float2*)&orow[t0 + tcol] = o;
                }
            }
        }
    } else {
        #pragma unroll
        for (int mi = 0; mi < 4; mi++) {
            #pragma unroll
            for (int half = 0; half < 2; half++) {
                const int s = m0 - CC + wm * 64 + mi * 16 + (lane >> 2) + half * 8;
                const float sbv = sbias[s];
                float* __restrict__ orow =
                    out + (size_t)BB * CC * TT + ((size_t)b * SS + s) * TT;
                #pragma unroll
                for (int ni = 0; ni < 4; ni++) {
                    const int t = t0 + wn * 32 + ni * 8 + (lane & 3) * 2;
                    float2 o;
                    o.x = acc[mi][ni][half * 2]     + sbv;
                    o.y = acc[mi][ni][half * 2 + 1] + sbv;
                    *(float2*)&orow[t] = o;
                }
            }
        }
    }
}

// ---------------- launch -----------------------------------------------------
extern "C" void kernel_launch(void* const* d_in, const int* in_sizes, int n_in,
                              void* d_out, int out_size)
{
    const float* x  = (const float*)d_in[0];
    const float* fw = (const float*)d_in[1];
    const float* fb = (const float*)d_in[2];
    const float* gw = (const float*)d_in[3];
    const float* gb = (const float*)d_in[4];
    const float* rw = (const float*)d_in[5];
    const float* rb = (const float*)d_in[6];
    const float* sw = (const float*)d_in[7];
    const float* sb = (const float*)d_in[8];
    float* out = (float*)d_out;

    cudaFuncSetAttribute(gemm1, cudaFuncAttributeMaxDynamicSharedMemorySize, SMEM_DYN);
    cudaFuncSetAttribute(gemm2, cudaFuncAttributeMaxDynamicSharedMemorySize, SMEM_DYN);

    transpose_x<<<dim3(TT / 64, CC / 64, BB), 256>>>(x);
    pack_w<<<(M1 * K1 + 255) / 256, 256>>>(fw, gw, rw, sw);
    gemm1<<<dim3(M1 / 128, NTOT / 128), 256, SMEM_DYN>>>(fb, gb);
    gemm2<<<dim3(M2 / 128, NTOT / 128), 256, SMEM_DYN>>>(x, rb, sb, out);
}

// round 16
// speedup vs baseline: 1.0364x; 1.0161x over previous
#include <cuda_runtime.h>
#include <cuda_fp16.h>
#include <stdint.h>
#include <math.h>

// ---------------- problem constants ----------------------------------------
#define BB   8
#define CC   512
#define SS   256
#define TT   8192
#define DIL  4
#define NTOT (BB*TT)       // 65536
#define K1   (2*CC)        // 1024 reduction dim GEMM1
#define M1   (2*CC)        // 1024 rows of W1 (F/G interleaved)
#define M2   (CC+SS)       // 768 rows GEMM2
#define KC   64            // k halfs per smem stage (4 mma k-steps of 16)
#define HST  72            // smem row stride in halfs (144B): conflict-free
#define NST  3             // pipeline stages
#define SZT  72            // gemm1 z-staging stride (halfs)
#define SQRT_HALF 0.70710678118654752440f

// ---------------- device scratch --------------------------------------------
__device__ __align__(16) __half g_xT[(size_t)NTOT*CC];  // [b][t][c]
__device__ __align__(16) __half g_zT[(size_t)NTOT*CC];  // [b][t][c]
__device__ __align__(16) __half g_W1[M1*K1];            // [o=2c+g][k]
__device__ __align__(16) __half g_W2[M2*CC];            // [m][k]
__device__ __align__(16) __half g_zero[16];             // zero-init (causal pad)

// ---------------- helpers ----------------------------------------------------
__device__ __forceinline__ void mma16(float* c, const uint32_t* a, const uint32_t* b) {
    asm volatile(
        "mma.sync.aligned.m16n8k16.row.col.f32.f16.f16.f32 "
        "{%0,%1,%2,%3}, {%4,%5,%6,%7}, {%8,%9}, {%0,%1,%2,%3};"
        : "+f"(c[0]), "+f"(c[1]), "+f"(c[2]), "+f"(c[3])
        : "r"(a[0]), "r"(a[1]), "r"(a[2]), "r"(a[3]), "r"(b[0]), "r"(b[1]));
}
__device__ __forceinline__ void cpa16(uint32_t dst, const void* src) {
    asm volatile("cp.async.cg.shared.global [%0], [%1], 16;" :: "r"(dst), "l"(src));
}
#define CP_COMMIT() asm volatile("cp.async.commit_group;" ::: "memory")
#define CP_WAIT1()  asm volatile("cp.async.wait_group 1;" ::: "memory")
#define CP_WAIT0()  asm volatile("cp.async.wait_group 0;" ::: "memory")

#define STAGE (128*HST)                     // halfs per operand stage (9216)
#define STAGE_B 18432                       // bytes per operand stage
#define SMEM_DYN (2*NST*STAGE*2)            // bytes: A[NST] + B[NST] (110592)

// ---------------- transpose: x[b][c][t] fp32 -> xT[b][t][c] fp16 -------------
__global__ void __launch_bounds__(256)
transpose_x(const float* __restrict__ x) {
    __shared__ float tile[64][65];
    const int b = blockIdx.z, c0 = blockIdx.y * 64, t0 = blockIdx.x * 64;
    const int tid = threadIdx.x;
    {
        const int row = tid >> 2, seg = (tid & 3) * 16;
        const float* src = x + ((size_t)b * CC + c0 + row) * TT + t0 + seg;
        #pragma unroll
        for (int i = 0; i < 4; i++) {
            float4 v = *(const float4*)(src + i * 4);
            tile[row][seg + i * 4 + 0] = v.x;
            tile[row][seg + i * 4 + 1] = v.y;
            tile[row][seg + i * 4 + 2] = v.z;
            tile[row][seg + i * 4 + 3] = v.w;
        }
    }
    __syncthreads();
    {
        const int trow = tid >> 2, seg = (tid & 3) * 16;
        __half* dst = g_xT + ((size_t)b * TT + t0 + trow) * CC + c0 + seg;
        #pragma unroll
        for (int i = 0; i < 2; i++) {
            __half h[8];
            #pragma unroll
            for (int j = 0; j < 8; j++)
                h[j] = __float2half_rn(tile[seg + i * 8 + j][trow]);
            *(uint4*)(dst + i * 8) = *(const uint4*)h;
        }
    }
}

// ---------------- merged weight pack -----------------------------------------
__global__ void pack_w(const float* __restrict__ fw, const float* __restrict__ gw,
                       const float* __restrict__ rw, const float* __restrict__ sw) {
    int idx = blockIdx.x * blockDim.x + threadIdx.x;
    if (idx < M1 * K1) {
        int o = idx / K1, k = idx % K1;
        int co = o >> 1, ci = k & (CC - 1);
        int tap = (k < CC) ? 1 : 0;
        const float* w = (o & 1) ? gw : fw;
        g_W1[idx] = __float2half_rn(w[(co * CC + ci) * 2 + tap]);
    }
    if (idx < M2 * CC) {
        int m = idx / CC, k = idx % CC;
        g_W2[idx] = __float2half_rn((m < CC) ? rw[m * CC + k] : sw[(m - CC) * CC + k]);
    }
}

// ---------------- GEMM1: D[t][2c+g] = xT2 @ W1^T, fused gating --------------
// CTA 128(t) x 128(interleaved outch); 8 warps 2x4; warp tile 64x32. fp16 MMA.
// Epilogue: gate -> smem stage -> coalesced 128B row writes.
__global__ void __launch_bounds__(256, 2)
gemm1(const float* __restrict__ fbias, const float* __restrict__ gbias)
{
    extern __shared__ __half hsm[];
    __half* sA = hsm;                  // [NST][128*HST]
    __half* sB = hsm + NST * STAGE;

    const int tid = threadIdx.x, lane = tid & 31, wid = tid >> 5;
    const int wm = wid >> 2, wn = wid & 3;
    const int nb = blockIdx.x;
    const int tb = blockIdx.y;
    const int base = tb * 128;
    const int b = base / TT;
    const int t0 = base % TT;
    const int n0 = nb * 128;
    const __half* __restrict__ xTb = g_xT + (size_t)b * TT * CC;

    const uint32_t sA_u = (uint32_t)__cvta_generic_to_shared(sA);
    const uint32_t sB_u = (uint32_t)__cvta_generic_to_shared(sB);

    float acc[4][4][4];
    #pragma unroll
    for (int i = 0; i < 4; i++)
        #pragma unroll
        for (int j = 0; j < 4; j++)
            #pragma unroll
            for (int q = 0; q < 4; q++) acc[i][j][q] = 0.f;

    const int arow = tid >> 3, ac8 = (tid & 7) * 8;
    auto issue = [&](int st, int k0) {
        const int sh = (k0 >= CC) ? DIL : 0;
        const int kk = k0 & (CC - 1);
        #pragma unroll
        for (int i = 0; i < 4; i++) {
            int row = arow + i * 32;
            int t = t0 + row - sh;
            const __half* srcA = (t >= 0) ? &xTb[(size_t)t * CC + kk + ac8]
                                          : &g_zero[0];
            cpa16(sA_u + (st * STAGE + row * HST + ac8) * 2, srcA);
            cpa16(sB_u + (st * STAGE + row * HST + ac8) * 2,
                  &g_W1[(size_t)(n0 + row) * K1 + k0 + ac8]);
        }
    };

    issue(0, 0);  CP_COMMIT();
    issue(1, KC); CP_COMMIT();

    const int aoff = (wm * 64 + (lane >> 2)) * HST + (lane & 3) * 2;
    const int boff = (wn * 32 + (lane >> 2)) * HST + (lane & 3) * 2;

    const int NC = K1 / KC;   // 16
    int st = 0;
    for (int c = 0; c < NC; c++) {
        CP_WAIT1();
        __syncthreads();
        const __half* a  = sA + st * STAGE + aoff;
        const __half* bs = sB + st * STAGE + boff;
        #pragma unroll
        for (int ks = 0; ks < 4; ks++) {
            const int kc = ks * 16;
            uint32_t af[4][4], bf[4][2];
            #pragma unroll
            for (int mi = 0; mi < 4; mi++) {
                const __half* p = a + mi * 16 * HST + kc;
                af[mi][0] = *(const uint32_t*)(p);
                af[mi][1] = *(const uint32_t*)(p + 8 * HST);
                af[mi][2] = *(const uint32_t*)(p + 8);
                af[mi][3] = *(const uint32_t*)(p + 8 * HST + 8);
            }
            #pragma unroll
            for (int ni = 0; ni < 4; ni++) {
                const __half* p = bs + ni * 8 * HST + kc;
                bf[ni][0] = *(const uint32_t*)(p);
                bf[ni][1] = *(const uint32_t*)(p + 8);
            }
            #pragma unroll
            for (int mi = 0; mi < 4; mi++)
                #pragma unroll
                for (int ni = 0; ni < 4; ni++)
                    mma16(acc[mi][ni], af[mi], bf[ni]);
        }
        __syncthreads();
        if (c + 2 < NC) issue((c + 2) % NST, (c + 2) * KC);
        CP_COMMIT();
        st = (st + 1) % NST;
    }
    // last iteration ended with a sync after all fragment reads: smem reusable.

    // ---- epilogue: gate -> smem stage -> coalesced 16B row writes -----------
    __half* sz = hsm;                             // [128][SZT]
    #pragma unroll
    for (int mi = 0; mi < 4; mi++) {
        const int tl = wm * 64 + mi * 16 + (lane >> 2);
        #pragma unroll
        for (int ni = 0; ni < 4; ni++) {
            const int chl = wn * 16 + ni * 4 + (lane & 3);
            const int ch = nb * 64 + chl;
            const float fb = fbias[ch], gb = gbias[ch];
            float F0 = acc[mi][ni][0] + fb;
            float G0 = acc[mi][ni][1] + gb;
            float F1 = acc[mi][ni][2] + fb;
            float G1 = acc[mi][ni][3] + gb;
            sz[tl * SZT + chl] =
                __float2half_rn(tanhf(F0) * (1.f / (1.f + __expf(-G0))));
            sz[(tl + 8) * SZT + chl] =
                __float2half_rn(tanhf(F1) * (1.f / (1.f + __expf(-G1))));
        }
    }
    __syncthreads();
    __half* __restrict__ zb = g_zT + (size_t)b * TT * CC;
    #pragma unroll
    for (int i = 0; i < 4; i++) {
        int f4 = tid + i * 256;
        int trow = f4 >> 3, c8 = f4 & 7;          // 8 uint4 per 64-half row
        *(uint4*)&zb[(size_t)(t0 + trow) * CC + nb * 64 + c8 * 8] =
            *(const uint4*)&sz[trow * SZT + c8 * 8];
    }
}

// ---------------- GEMM2: D[m][t] = W2 @ zT^T, fused residual/skip -----------
// CTA 128(m) x 128(t); 8 warps 2x4; warp tile 64x32. fp16 MMA.
// Residual x tile prefetched into freed pipeline stages during final 2 chunks.
__global__ void __launch_bounds__(256, 2)
gemm2(const float* __restrict__ x,
      const float* __restrict__ rbias, const float* __restrict__ sbias,
      float* __restrict__ out)
{
    extern __shared__ __half hsm[];
    __half* sA = hsm;
    __half* sB = hsm + NST * STAGE;

    const int tid = threadIdx.x, lane = tid & 31, wid = tid >> 5;
    const int wm = wid >> 2, wn = wid & 3;
    const int mb = blockIdx.x;                    // 6 m-tiles
    const int tb = blockIdx.y;                    // 512 t-tiles
    const int base = tb * 128;
    const int b = base / TT;
    const int t0 = base % TT;
    const int m0 = mb * 128;
    const bool isRes = (m0 < CC);                 // whole tile residual or skip
    const __half* __restrict__ zTb = g_zT + (size_t)b * TT * CC;

    const uint32_t sA_u = (uint32_t)__cvta_generic_to_shared(sA);
    const uint32_t sB_u = (uint32_t)__cvta_generic_to_shared(sB);

    // x staging byte offset for row r (512B rows packed into freed stages)
    auto xoff = [](int r) -> uint32_t {
        if (r < 36)  return 2u * STAGE_B + (uint32_t)r * 512u;
        if (r < 72)  return 3u * STAGE_B + 2u * STAGE_B + (uint32_t)(r - 36) * 512u;
        if (r < 108) return (uint32_t)(r - 72) * 512u;
        return 3u * STAGE_B + (uint32_t)(r - 108) * 512u;
    };

    float acc[4][4][4];
    #pragma unroll
    for (int i = 0; i < 4; i++)
        #pragma unroll
        for (int j = 0; j < 4; j++)
            #pragma unroll
            for (int q = 0; q < 4; q++) acc[i][j][q] = 0.f;

    const int arow = tid >> 3, ac8 = (tid & 7) * 8;
    auto issue = [&](int st, int k0) {
        #pragma unroll
        for (int i = 0; i < 4; i++) {
            int row = arow + i * 32;
            cpa16(sA_u + (st * STAGE + row * HST + ac8) * 2,
                  &g_W2[(size_t)(m0 + row) * CC + k0 + ac8]);
            cpa16(sB_u + (st * STAGE + row * HST + ac8) * 2,
                  &zTb[(size_t)(t0 + row) * CC + k0 + ac8]);
        }
    };

    issue(0, 0);  CP_COMMIT();
    issue(1, KC); CP_COMMIT();

    const int aoff = (wm * 64 + (lane >> 2)) * HST + (lane & 3) * 2;
    const int boff = (wn * 32 + (lane >> 2)) * HST + (lane & 3) * 2;

    const int NC = CC / KC;   // 8
    int st = 0;
    for (int c = 0; c < NC; c++) {
        CP_WAIT1();
        __syncthreads();
        const __half* a  = sA + st * STAGE + aoff;
        const __half* bs = sB + st * STAGE + boff;
        #pragma unroll
        for (int ks = 0; ks < 4; ks++) {
            const int kc = ks * 16;
            uint32_t af[4][4], bf[4][2];
            #pragma unroll
            for (int mi = 0; mi < 4; mi++) {
                const __half* p = a + mi * 16 * HST + kc;
                af[mi][0] = *(const uint32_t*)(p);
                af[mi][1] = *(const uint32_t*)(p + 8 * HST);
                af[mi][2] = *(const uint32_t*)(p + 8);
                af[mi][3] = *(const uint32_t*)(p + 8 * HST + 8);
            }
            #pragma unroll
            for (int ni = 0; ni < 4; ni++) {
                const __half* p = bs + ni * 8 * HST + kc;
                bf[ni][0] = *(const uint32_t*)(p);
                bf[ni][1] = *(const uint32_t*)(p + 8);
            }
            #pragma unroll
            for (int mi = 0; mi < 4; mi++)
                #pragma unroll
                for (int ni = 0; ni < 4; ni++)
                    mma16(acc[mi][ni], af[mi], bf[ni]);
        }
        __syncthreads();
        if (c + 2 < NC) {
            issue((c + 2) % NST, (c + 2) * KC);
        } else if (isRes) {
            const int r0 = (c == NC - 2) ? 0 : 72;
            const int nops = ((c == NC - 2) ? 72 : 56) * 32;
            for (int i = tid; i < nops; i += 256) {
                const int r = r0 + (i >> 5);
                const int l16 = i & 31;
                cpa16(sA_u + xoff(r) + l16 * 16,
                      &x[((size_t)b * CC + m0 + r) * TT + t0 + l16 * 4]);
            }
        }
        CP_COMMIT();
        st = (st + 1) % NST;
    }

    // ---- epilogue ------------------------------------------------------------
    if (isRes) {
        CP_WAIT0();
        __syncthreads();
        const char* sxb = (const char*)hsm;
        #pragma unroll
        for (int mi = 0; mi < 4; mi++) {
            #pragma unroll
            for (int half = 0; half < 2; half++) {
                const int r = wm * 64 + mi * 16 + (lane >> 2) + half * 8;
                const int m = m0 + r;
                const float rbv = rbias[m];
                float* __restrict__ orow = out + ((size_t)b * CC + m) * TT;
                const uint32_t xo = xoff(r);
                #pragma unroll
                for (int ni = 0; ni < 4; ni++) {
                    const int tcol = wn * 32 + ni * 8 + (lane & 3) * 2;
                    float2 xv = *(const float2*)(sxb + xo + tcol * 4);
                    float2 o;
                    o.x = (xv.x + acc[mi][ni][half * 2]     + rbv) * SQRT_HALF;
                    o.y = (xv.y + acc[mi][ni][half * 2 + 1] + rbv) * SQRT_HALF;
                    *(float2*)&orow[t0 + tcol] = o;
                }
            }
        }
    } else {
        #pragma unroll
        for (int mi = 0; mi < 4; mi++) {
            #pragma unroll
            for (int half = 0; half < 2; half++) {
                const int s = m0 - CC + wm * 64 + mi * 16 + (lane >> 2) + half * 8;
                const float sbv = sbias[s];
                float* __restrict__ orow =
                    out + (size_t)BB * CC * TT + ((size_t)b * SS + s) * TT;
                #pragma unroll
                for (int ni = 0; ni < 4; ni++) {
                    const int t = t0 + wn * 32 + ni * 8 + (lane & 3) * 2;
                    float2 o;
                    o.x = acc[mi][ni][half * 2]     + sbv;
                    o.y = acc[mi][ni][half * 2 + 1] + sbv;
                    *(float2*)&orow[t] = o;
                }
            }
        }
    }
}

// ---------------- launch -----------------------------------------------------
extern "C" void kernel_launch(void* const* d_in, const int* in_sizes, int n_in,
                              void* d_out, int out_size)
{
    const float* x  = (const float*)d_in[0];
    const float* fw = (const float*)d_in[1];
    const float* fb = (const float*)d_in[2];
    const float* gw = (const float*)d_in[3];
    const float* gb = (const float*)d_in[4];
    const float* rw = (const float*)d_in[5];
    const float* rb = (const float*)d_in[6];
    const float* sw = (const float*)d_in[7];
    const float* sb = (const float*)d_in[8];
    float* out = (float*)d_out;

    cudaFuncSetAttribute(gemm1, cudaFuncAttributeMaxDynamicSharedMemorySize, SMEM_DYN);
    cudaFuncSetAttribute(gemm2, cudaFuncAttributeMaxDynamicSharedMemorySize, SMEM_DYN);

    transpose_x<<<dim3(TT / 64, CC / 64, BB), 256>>>(x);
    pack_w<<<(M1 * K1 + 255) / 256, 256>>>(fw, gw, rw, sw);
    gemm1<<<dim3(M1 / 128, NTOT / 128), 256, SMEM_DYN>>>(fb, gb);
    gemm2<<<dim3(M2 / 128, NTOT / 128), 256, SMEM_DYN>>>(x, rb, sb, out);
}